// round 8
// baseline (speedup 1.0000x reference)
#include <cuda_runtime.h>
#include <cstdint>

#define N_NODES 64000
#define NPOINTS 2000
#define NB 32
#define TT 12
#define E_EDGES 1024000
#define GH 32
#define NO 8
#define HH 64
#define NBLK 148
#define NTH 384
#define TOTTH (NBLK * NTH)         // 56832
#define NGROUPS 3
#define NCHUNKS (NBLK * NGROUPS)   // 444
#define CHUNK 145                  // ceil(64000/444)
#define LOOKBACK 24
#define RING 32

// scratch (static device globals; no allocation at runtime)
__device__ float g_x11[N_NODES];
__device__ float g_agg1[N_NODES];
__device__ float g_y[N_NODES * NO];
__device__ float g_acc[(N_NODES + 64) * NO];   // pad for staging/prefetch reads
__device__ float g_wt[NB];
__device__ unsigned g_cnt = 0;
__device__ unsigned g_gen = 0;

// ---- packed f32x2 helpers -------------------------------------------------
__device__ __forceinline__ unsigned long long pack2(float lo, float hi) {
    unsigned long long r;
    asm("mov.b64 %0, {%1,%2};" : "=l"(r) : "f"(lo), "f"(hi));
    return r;
}
__device__ __forceinline__ unsigned long long fma2(unsigned long long a,
                                                   unsigned long long b,
                                                   unsigned long long c) {
    unsigned long long d;
    asm("fma.rn.f32x2 %0, %1, %2, %3;" : "=l"(d) : "l"(a), "l"(b), "l"(c));
    return d;
}
__device__ __forceinline__ float unpack_sum(unsigned long long v) {
    float lo, hi;
    asm("mov.b64 {%0,%1}, %2;" : "=f"(lo), "=f"(hi) : "l"(v));
    return lo + hi;
}
__device__ __forceinline__ float tanh_a(float x) {
    float y;
    asm("tanh.approx.f32 %0, %1;" : "=f"(y) : "f"(x));
    return y;
}
__device__ __forceinline__ void cp_async16(uint32_t smem_addr, const void* gptr) {
    asm volatile("cp.async.cg.shared.global [%0], [%1], 16;"
                 :: "r"(smem_addr), "l"(gptr) : "memory");
}
__device__ __forceinline__ void cp_commit() {
    asm volatile("cp.async.commit_group;" ::: "memory");
}
__device__ __forceinline__ void cp_wait0() {
    asm volatile("cp.async.wait_group 0;" ::: "memory");
}
__device__ __forceinline__ void red_add_v4(float* addr, float4 v) {
    asm volatile("red.global.add.v4.f32 [%0], {%1,%2,%3,%4};"
                 :: "l"(addr), "f"(v.x), "f"(v.y), "f"(v.z), "f"(v.w)
                 : "memory");
}
__device__ __forceinline__ void prefetch_l2(const void* p) {
    asm volatile("prefetch.global.L2 [%0];" :: "l"(p));
}

// ---- grid barrier (all 148 blocks co-resident: 1 block/SM) ----------------
__device__ __forceinline__ void grid_bar() {
    __syncthreads();
    if (threadIdx.x == 0) {
        __threadfence();
        unsigned g0 = *((volatile unsigned*)&g_gen);
        unsigned my = atomicAdd(&g_cnt, 1u);
        if (my == NBLK - 1) {
            g_cnt = 0;
            __threadfence();
            *((volatile unsigned*)&g_gen) = g0 + 1;
        } else {
            while (*((volatile unsigned*)&g_gen) == g0) __nanosleep(32);
        }
        __threadfence();
    }
    __syncthreads();
}

#define GBAR(gid) asm volatile("bar.sync %0, 128;" :: "r"((gid) + 1) : "memory")

// ---------------------------------------------------------------------------
// ONE persistent kernel: prep | scatter1 | node | scatter2 | lstm, separated
// by grid barriers. 148 blocks x 384 threads (1 block/SM).
// ---------------------------------------------------------------------------
__global__ void __launch_bounds__(NTH, 1) fused_kernel(
    const float* __restrict__ x, const int* __restrict__ ei,
    const float* __restrict__ weather, const float* __restrict__ timeenc,
    const float* __restrict__ W1rel, const float* __restrict__ b1,
    const float* __restrict__ W1root, const float* __restrict__ W2rel,
    const float* __restrict__ b2, const float* __restrict__ W2root,
    const float* __restrict__ Wih, const float* __restrict__ Whh,
    const float* __restrict__ bih, const float* __restrict__ bhh,
    const float* __restrict__ Wlin, const float* __restrict__ blin,
    float* __restrict__ out) {
    // -------- shared --------
    __shared__ __align__(16) float hring[NGROUPS][RING][68];
    __shared__ __align__(16) float xtile[NGROUPS][2][RING * NO];
    __shared__ float swlin[HH];
    __shared__ float sW1rel[GH], sb1[GH], sW1root[GH];
    __shared__ float sW2rel[GH * NO], sW2root[GH * NO], sb2[NO];

    int tid = threadIdx.x;
    int bid = blockIdx.x;
    int gtid = bid * NTH + tid;

    // ================= P0: prep (+ L2 prefetch of LSTM weights) ============
    for (int n = gtid; n < N_NODES; n += TOTTH) {
        int b = n / NPOINTS;
        int p = n - b * NPOINTS;
        g_x11[n] = x[b * (TT * NPOINTS) + 11 * NPOINTS + p];
        g_agg1[n] = 0.f;
    }
    if (bid == 0 && tid < NB) {
        int b = tid;
        float s = __ldg(&blin[0]);
        #pragma unroll
        for (int j = 0; j < 4; j++)
            s += weather[b * TT * 4 + 11 * 4 + j] * Wlin[64 + j];
        #pragma unroll
        for (int j = 0; j < 8; j++)
            s += timeenc[b * TT * 8 + 11 * 8 + j] * Wlin[68 + j];
        g_wt[b] = s;   // full weather/time/bias scalar per batch row
    }
    // prefetch Whh (64KB) + Wih (8KB) into L2
    if (gtid < 512) prefetch_l2((const char*)Whh + gtid * 128);
    if (gtid >= 512 && gtid < 576) prefetch_l2((const char*)Wih + (gtid - 512) * 128);
    grid_bar();

    // ================= P1: scatter1 (agg1[dst] += x11[src]) ================
    for (int i = gtid; i < E_EDGES / 4; i += TOTTH) {
        int4 s4 = ((const int4*)ei)[i];
        int4 d4 = ((const int4*)(ei + E_EDGES))[i];
        atomicAdd(&g_agg1[d4.x], __ldg(&g_x11[s4.x]));
        atomicAdd(&g_agg1[d4.y], __ldg(&g_x11[s4.y]));
        atomicAdd(&g_agg1[d4.z], __ldg(&g_x11[s4.z]));
        atomicAdd(&g_agg1[d4.w], __ldg(&g_x11[s4.w]));
    }
    grid_bar();

    // ================= P2: node MLP ========================================
    if (tid < GH) {
        sW1rel[tid] = W1rel[tid];
        sb1[tid] = b1[tid];
        sW1root[tid] = W1root[tid];
    }
    if (tid < GH * NO) {
        sW2rel[tid] = W2rel[tid];
        sW2root[tid] = W2root[tid];
    }
    if (tid < NO) sb2[tid] = b2[tid];
    __syncthreads();
    for (int n = gtid; n < N_NODES; n += TOTTH) {
        float a = __ldcg(&g_agg1[n]);
        float xv = g_x11[n];
        float y[NO], p[NO];
        #pragma unroll
        for (int j = 0; j < NO; j++) { y[j] = 0.f; p[j] = sb2[j]; }
        #pragma unroll
        for (int k = 0; k < GH; k++) {
            float h1 = fmaf(a, sW1rel[k], fmaf(xv, sW1root[k], sb1[k]));
            h1 = fmaxf(h1, 0.f);
            #pragma unroll
            for (int j = 0; j < NO; j++) {
                y[j] = fmaf(h1, sW2rel[k * NO + j], y[j]);
                p[j] = fmaf(h1, sW2root[k * NO + j], p[j]);
            }
        }
        float4* yp = (float4*)&g_y[n * NO];
        yp[0] = make_float4(y[0], y[1], y[2], y[3]);
        yp[1] = make_float4(y[4], y[5], y[6], y[7]);
        float4* ap = (float4*)&g_acc[n * NO];
        ap[0] = make_float4(p[0], p[1], p[2], p[3]);
        ap[1] = make_float4(p[4], p[5], p[6], p[7]);
        out[n] = __ldcg(&g_wt[n & (NB - 1)]);
    }
    grid_bar();

    // ================= P3: scatter2 (acc[dst] += y[src], v4 reds) ==========
    for (int e = gtid; e < E_EDGES; e += TOTTH) {
        int s = __ldg(&ei[e]);
        int d = __ldg(&ei[E_EDGES + e]);
        float4 va = __ldcg((const float4*)&g_y[s * NO]);
        float4 vb = __ldcg((const float4*)&g_y[s * NO + 4]);
        red_add_v4(&g_acc[d * NO], va);
        red_add_v4(&g_acc[d * NO + 4], vb);
    }
    grid_bar();

    // ================= P4: LSTM scan =======================================
    int g = tid >> 7;            // group 0..2
    int lt = tid & 127;          // thread within group
    int l = tid & 31;
    int wl = (tid >> 5) & 3;     // warp within group
    int j = wl * 16 + (l >> 1);  // hidden unit
    int p = l & 1;               // gate-pair selector
    int gidxA = (2 * p) * 64 + j;        // p=0: i ; p=1: g
    int gidxB = gidxA + 64;              // p=0: f ; p=1: o

    // packed weights over the reduction dim (L2-hot from P0 prefetch)
    unsigned long long whhA[HH / 2], whhB[HH / 2];
    #pragma unroll
    for (int k = 0; k < HH / 2; k++) {
        whhA[k] = pack2(__ldg(&Whh[(2 * k) * 256 + gidxA]),
                        __ldg(&Whh[(2 * k + 1) * 256 + gidxA]));
        whhB[k] = pack2(__ldg(&Whh[(2 * k) * 256 + gidxB]),
                        __ldg(&Whh[(2 * k + 1) * 256 + gidxB]));
    }
    unsigned long long wihA[NO / 2], wihB[NO / 2];
    #pragma unroll
    for (int k = 0; k < NO / 2; k++) {
        wihA[k] = pack2(__ldg(&Wih[(2 * k) * 256 + gidxA]),
                        __ldg(&Wih[(2 * k + 1) * 256 + gidxA]));
        wihB[k] = pack2(__ldg(&Wih[(2 * k) * 256 + gidxB]),
                        __ldg(&Wih[(2 * k + 1) * 256 + gidxB]));
    }
    float bA = __ldg(&bih[gidxA]) + __ldg(&bhh[gidxA]);
    float bB = __ldg(&bih[gidxB]) + __ldg(&bhh[gidxB]);
    float mA = p ? 1.f : 0.5f;
    float kA = p ? 0.f : 0.5f;

    for (int k = lt; k < RING * 68; k += 128)
        ((float*)hring[g])[k] = 0.f;
    if (tid < HH) swlin[tid] = __ldg(&Wlin[tid]);
    __syncthreads();   // whole block once; groups independent afterwards

    int chunk = bid * NGROUPS + g;
    int start = chunk * CHUNK;
    if (start >= N_NODES) return;   // whole group exits uniformly
    int end = start + CHUNK;
    if (end > N_NODES) end = N_NODES;
    int s0 = start - LOOKBACK;
    if (s0 < 0) s0 = 0;

    // prime double-buffered x staging: window(s0) and window(s0)+1
    {
        int w0 = s0 & ~(RING - 1);
        int b0 = (s0 >> 5) & 1;
        if (lt < 64) {
            uint32_t dst0 = (uint32_t)__cvta_generic_to_shared(&xtile[g][b0][lt * 4]);
            cp_async16(dst0, &g_acc[w0 * NO + lt * 4]);
            cp_commit();
            uint32_t dst1 = (uint32_t)__cvta_generic_to_shared(&xtile[g][b0 ^ 1][lt * 4]);
            cp_async16(dst1, &g_acc[(w0 + RING) * NO + lt * 4]);
            cp_commit();
        }
        cp_wait0();
        GBAR(g);
    }

    float c = 0.f;

    for (int n = s0; n < end; n++) {
        int r = n & (RING - 1);
        int buf = (n >> 5) & 1;
        if (r == 0 && n != s0) {
            cp_wait0();
            GBAR(g);
            if (lt < 64) {
                uint32_t dst = (uint32_t)__cvta_generic_to_shared(&xtile[g][buf ^ 1][lt * 4]);
                cp_async16(dst, &g_acc[(n + RING) * NO + lt * 4]);
                cp_commit();
            }
        }
        const ulonglong2* xp = (const ulonglong2*)&xtile[g][buf][r * NO];
        ulonglong2 xv0 = xp[0];
        ulonglong2 xv1 = xp[1];
        unsigned long long aA = pack2(bA, 0.f);
        unsigned long long aB = pack2(bB, 0.f);
        aA = fma2(xv0.x, wihA[0], aA); aB = fma2(xv0.x, wihB[0], aB);
        aA = fma2(xv0.y, wihA[1], aA); aB = fma2(xv0.y, wihB[1], aB);
        aA = fma2(xv1.x, wihA[2], aA); aB = fma2(xv1.x, wihB[2], aB);
        aA = fma2(xv1.y, wihA[3], aA); aB = fma2(xv1.y, wihB[3], aB);
        const ulonglong2* hp = (const ulonglong2*)hring[g][(n - 1) & (RING - 1)];
        #pragma unroll
        for (int k = 0; k < 16; k++) {
            ulonglong2 hv = hp[k];   // dual-broadcast LDS.128
            aA = fma2(hv.x, whhA[2 * k + 0], aA);
            aA = fma2(hv.y, whhA[2 * k + 1], aA);
            aB = fma2(hv.x, whhB[2 * k + 0], aB);
            aB = fma2(hv.y, whhB[2 * k + 1], aB);
        }
        float sA = unpack_sum(aA);
        float sB = unpack_sum(aB);
        float actA = fmaf(mA, tanh_a(sA * mA), kA);
        float actB = fmaf(0.5f, tanh_a(0.5f * sB), 0.5f);
        float rAv = __shfl_xor_sync(0xffffffffu, actA, 1);
        float rBv = __shfl_xor_sync(0xffffffffu, actB, 1);
        float iv = p ? rAv : actA;
        float fv = p ? rBv : actB;
        float gv = p ? actA : rAv;
        float ov = p ? actB : rBv;
        c = fmaf(fv, c, iv * gv);
        float hn = ov * tanh_a(c);
        if (p == 0) hring[g][r][j] = hn;
        GBAR(g);

        if (r == RING - 1 || n == end - 1) {
            int w0 = n & ~(RING - 1);
            int nn = w0 + (lt >> 2);
            int q = lt & 3;
            const float* hrow = hring[g][lt >> 2];
            float acc = 0.f;
            #pragma unroll
            for (int k = 0; k < 16; k++)
                acc = fmaf(hrow[q * 16 + k], swlin[q * 16 + k], acc);
            acc += __shfl_xor_sync(0xffffffffu, acc, 1);
            acc += __shfl_xor_sync(0xffffffffu, acc, 2);
            if (q == 0 && nn >= start && nn < end)
                out[nn] += acc;
        }
    }
}

// ---------------------------------------------------------------------------
extern "C" void kernel_launch(void* const* d_in, const int* in_sizes, int n_in,
                              void* d_out, int out_size) {
    const float* x        = (const float*)d_in[0];
    const int*   ei       = (const int*)  d_in[1];
    const float* weather  = (const float*)d_in[2];
    const float* timeenc  = (const float*)d_in[3];
    const float* W1rel    = (const float*)d_in[4];
    const float* b1       = (const float*)d_in[5];
    const float* W1root   = (const float*)d_in[6];
    const float* W2rel    = (const float*)d_in[7];
    const float* b2       = (const float*)d_in[8];
    const float* W2root   = (const float*)d_in[9];
    const float* Wih      = (const float*)d_in[10];
    const float* Whh      = (const float*)d_in[11];
    const float* bih      = (const float*)d_in[12];
    const float* bhh      = (const float*)d_in[13];
    const float* Wlin     = (const float*)d_in[14];
    const float* blin     = (const float*)d_in[15];
    float* out = (float*)d_out;

    fused_kernel<<<NBLK, NTH>>>(x, ei, weather, timeenc, W1rel, b1, W1root,
                                W2rel, b2, W2root, Wih, Whh, bih, bhh,
                                Wlin, blin, out);
}

// round 9
// speedup vs baseline: 1.2345x; 1.2345x over previous
#include <cuda_runtime.h>
#include <cstdint>

#define N_NODES 64000
#define NPOINTS 2000
#define NB 32
#define TT 12
#define E_EDGES 1024000
#define GH 32
#define NO 8
#define HH 64
#define NBLK 148
#define NGROUPS 3
#define NCHUNKS (NBLK * NGROUPS)   // 444
#define CHUNK 145                  // ceil(64000/444)
#define LOOKBACK 16
#define RING 32

// scratch (static device globals; no allocation at runtime)
__device__ float g_x11[N_NODES];
__device__ float g_agg1[N_NODES];
__device__ float g_y[N_NODES * NO];
__device__ float g_acc[(N_NODES + 64) * NO];   // pad for staging/prefetch reads
__device__ float g_wt[NB];

// ---- packed f32x2 helpers -------------------------------------------------
__device__ __forceinline__ unsigned long long pack2(float lo, float hi) {
    unsigned long long r;
    asm("mov.b64 %0, {%1,%2};" : "=l"(r) : "f"(lo), "f"(hi));
    return r;
}
__device__ __forceinline__ unsigned long long fma2(unsigned long long a,
                                                   unsigned long long b,
                                                   unsigned long long c) {
    unsigned long long d;
    asm("fma.rn.f32x2 %0, %1, %2, %3;" : "=l"(d) : "l"(a), "l"(b), "l"(c));
    return d;
}
__device__ __forceinline__ float unpack_sum(unsigned long long v) {
    float lo, hi;
    asm("mov.b64 {%0,%1}, %2;" : "=f"(lo), "=f"(hi) : "l"(v));
    return lo + hi;
}
__device__ __forceinline__ float tanh_a(float x) {
    float y;
    asm("tanh.approx.f32 %0, %1;" : "=f"(y) : "f"(x));
    return y;
}
__device__ __forceinline__ void cp_async16(uint32_t smem_addr, const void* gptr) {
    asm volatile("cp.async.cg.shared.global [%0], [%1], 16;"
                 :: "r"(smem_addr), "l"(gptr) : "memory");
}
__device__ __forceinline__ void cp_commit() {
    asm volatile("cp.async.commit_group;" ::: "memory");
}
__device__ __forceinline__ void cp_wait0() {
    asm volatile("cp.async.wait_group 0;" ::: "memory");
}
__device__ __forceinline__ void prefetch_l2(const void* p) {
    asm volatile("prefetch.global.L2 [%0];" :: "l"(p));
}

// ---------------------------------------------------------------------------
// K1: extract x at t=11, zero agg1, weather/time scalar, prefetch LSTM weights
// ---------------------------------------------------------------------------
__global__ void prep_kernel(const float* __restrict__ x,
                            const float* __restrict__ weather,
                            const float* __restrict__ timeenc,
                            const float* __restrict__ Wlin,
                            const float* __restrict__ blin,
                            const float* __restrict__ Wih,
                            const float* __restrict__ Whh) {
    int n = blockIdx.x * blockDim.x + threadIdx.x;
    if (n < N_NODES) {
        int b = n / NPOINTS;
        int p = n - b * NPOINTS;
        g_x11[n] = x[b * (TT * NPOINTS) + 11 * NPOINTS + p];
        g_agg1[n] = 0.f;
    }
    // warm L2 with LSTM weights (Whh 64KB, Wih 8KB)
    if (n < 512) prefetch_l2((const char*)Whh + n * 128);
    else if (n < 576) prefetch_l2((const char*)Wih + (n - 512) * 128);
    if (blockIdx.x == 0 && threadIdx.x < NB) {
        int b = threadIdx.x;
        float s = __ldg(&blin[0]);
        #pragma unroll
        for (int j = 0; j < 4; j++)
            s += weather[b * TT * 4 + 11 * 4 + j] * Wlin[64 + j];
        #pragma unroll
        for (int j = 0; j < 8; j++)
            s += timeenc[b * TT * 8 + 11 * 8 + j] * Wlin[68 + j];
        g_wt[b] = s;
    }
}

// ---------------------------------------------------------------------------
// K2: agg1[dst] += x11[src]
// ---------------------------------------------------------------------------
__global__ void scatter1_kernel(const int* __restrict__ ei) {
    int i = blockIdx.x * blockDim.x + threadIdx.x;
    if (i * 4 >= E_EDGES) return;
    int4 s4 = ((const int4*)ei)[i];
    int4 d4 = ((const int4*)(ei + E_EDGES))[i];
    atomicAdd(&g_agg1[d4.x], __ldg(&g_x11[s4.x]));
    atomicAdd(&g_agg1[d4.y], __ldg(&g_x11[s4.y]));
    atomicAdd(&g_agg1[d4.z], __ldg(&g_x11[s4.z]));
    atomicAdd(&g_agg1[d4.w], __ldg(&g_x11[s4.w]));
}

// ---------------------------------------------------------------------------
// K3: node MLP; writes y (edge payload), acc (root part), out init (= wt)
// ---------------------------------------------------------------------------
__global__ void node_kernel(const float* __restrict__ W1rel,
                            const float* __restrict__ b1,
                            const float* __restrict__ W1root,
                            const float* __restrict__ W2rel,
                            const float* __restrict__ b2,
                            const float* __restrict__ W2root,
                            float* __restrict__ out) {
    __shared__ float sW1rel[GH], sb1[GH], sW1root[GH];
    __shared__ float sW2rel[GH * NO], sW2root[GH * NO], sb2[NO];
    int tid = threadIdx.x;
    if (tid < GH) {
        sW1rel[tid] = W1rel[tid];
        sb1[tid] = b1[tid];
        sW1root[tid] = W1root[tid];
    }
    if (tid < GH * NO) {
        sW2rel[tid] = W2rel[tid];
        sW2root[tid] = W2root[tid];
    }
    if (tid < NO) sb2[tid] = b2[tid];
    __syncthreads();

    int n = blockIdx.x * blockDim.x + tid;
    if (n >= N_NODES) return;
    float a = g_agg1[n];
    float xv = g_x11[n];
    float y[NO], p[NO];
    #pragma unroll
    for (int j = 0; j < NO; j++) { y[j] = 0.f; p[j] = sb2[j]; }
    #pragma unroll
    for (int k = 0; k < GH; k++) {
        float h1 = fmaf(a, sW1rel[k], fmaf(xv, sW1root[k], sb1[k]));
        h1 = fmaxf(h1, 0.f);
        #pragma unroll
        for (int j = 0; j < NO; j++) {
            y[j] = fmaf(h1, sW2rel[k * NO + j], y[j]);
            p[j] = fmaf(h1, sW2root[k * NO + j], p[j]);
        }
    }
    float4* yp = (float4*)&g_y[n * NO];
    yp[0] = make_float4(y[0], y[1], y[2], y[3]);
    yp[1] = make_float4(y[4], y[5], y[6], y[7]);
    float4* ap = (float4*)&g_acc[n * NO];
    ap[0] = make_float4(p[0], p[1], p[2], p[3]);
    ap[1] = make_float4(p[4], p[5], p[6], p[7]);
    out[n] = g_wt[n & (NB - 1)];
}

// ---------------------------------------------------------------------------
// K4: acc[dst] += y[src]   (8 floats/edge, vector reductions)
// ---------------------------------------------------------------------------
__device__ __forceinline__ void red_add_v4(float* addr, float4 v) {
    asm volatile("red.global.add.v4.f32 [%0], {%1,%2,%3,%4};"
                 :: "l"(addr), "f"(v.x), "f"(v.y), "f"(v.z), "f"(v.w)
                 : "memory");
}

__global__ void scatter2_kernel(const int* __restrict__ ei) {
    int e = blockIdx.x * blockDim.x + threadIdx.x;
    if (e >= E_EDGES) return;
    int s = __ldg(&ei[e]);
    int d = __ldg(&ei[E_EDGES + e]);
    const float4* yp = (const float4*)&g_y[s * NO];
    float4 va = __ldg(yp);
    float4 vb = __ldg(yp + 1);
    red_add_v4(&g_acc[d * NO], va);
    red_add_v4(&g_acc[d * NO + 4], vb);
}

// ---------------------------------------------------------------------------
// K5: LSTM scan. 3 independent chains per block (named-barrier groups of
// 4 warps / 128 threads). Window-nested loop: outer over 32-node windows
// (staging / prefetch / flush), inner branch-free over steps.
// ---------------------------------------------------------------------------
#define GBAR(gid) asm volatile("bar.sync %0, 128;" :: "r"((gid) + 1) : "memory")

__global__ void __launch_bounds__(384, 1) lstm_kernel(
    const float* __restrict__ Wih, const float* __restrict__ Whh,
    const float* __restrict__ bih, const float* __restrict__ bhh,
    const float* __restrict__ Wlin, float* __restrict__ out) {
    __shared__ __align__(16) float hring[NGROUPS][RING][68];
    __shared__ __align__(16) float xtile[NGROUPS][2][RING * NO];
    __shared__ float swlin[HH];

    int tid = threadIdx.x;
    int g = tid >> 7;            // group 0..2
    int lt = tid & 127;          // thread within group
    int l = tid & 31;
    int wl = (tid >> 5) & 3;     // warp within group
    int j = wl * 16 + (l >> 1);  // hidden unit
    int p = l & 1;               // gate-pair selector
    int gidxA = (2 * p) * 64 + j;        // p=0: i ; p=1: g
    int gidxB = gidxA + 64;              // p=0: f ; p=1: o

    // packed weights over the reduction dim (64 ull = 128 regs, L2-hot)
    unsigned long long whhA[HH / 2], whhB[HH / 2];
    #pragma unroll
    for (int k = 0; k < HH / 2; k++) {
        whhA[k] = pack2(__ldg(&Whh[(2 * k) * 256 + gidxA]),
                        __ldg(&Whh[(2 * k + 1) * 256 + gidxA]));
        whhB[k] = pack2(__ldg(&Whh[(2 * k) * 256 + gidxB]),
                        __ldg(&Whh[(2 * k + 1) * 256 + gidxB]));
    }
    unsigned long long wihA[NO / 2], wihB[NO / 2];
    #pragma unroll
    for (int k = 0; k < NO / 2; k++) {
        wihA[k] = pack2(__ldg(&Wih[(2 * k) * 256 + gidxA]),
                        __ldg(&Wih[(2 * k + 1) * 256 + gidxA]));
        wihB[k] = pack2(__ldg(&Wih[(2 * k) * 256 + gidxB]),
                        __ldg(&Wih[(2 * k + 1) * 256 + gidxB]));
    }
    float bA = __ldg(&bih[gidxA]) + __ldg(&bhh[gidxA]);
    float bB = __ldg(&bih[gidxB]) + __ldg(&bhh[gidxB]);
    float mA = p ? 1.f : 0.5f;
    float kA = p ? 0.f : 0.5f;

    for (int k = lt; k < RING * 68; k += 128)
        ((float*)hring[g])[k] = 0.f;
    if (tid < HH) swlin[tid] = __ldg(&Wlin[tid]);
    __syncthreads();   // whole block once; groups independent afterwards

    int chunk = blockIdx.x * NGROUPS + g;
    int start = chunk * CHUNK;
    if (start >= N_NODES) return;   // whole group exits uniformly
    int end = start + CHUNK;
    if (end > N_NODES) end = N_NODES;
    int s0 = start - LOOKBACK;
    if (s0 < 0) s0 = 0;
    int wfirst = s0 & ~(RING - 1);

    // prime double-buffered x staging: windows wfirst and wfirst+RING
    {
        int b0 = (wfirst >> 5) & 1;
        if (lt < 64) {
            uint32_t dst0 = (uint32_t)__cvta_generic_to_shared(&xtile[g][b0][lt * 4]);
            cp_async16(dst0, &g_acc[wfirst * NO + lt * 4]);
            cp_commit();
            uint32_t dst1 = (uint32_t)__cvta_generic_to_shared(&xtile[g][b0 ^ 1][lt * 4]);
            cp_async16(dst1, &g_acc[(wfirst + RING) * NO + lt * 4]);
            cp_commit();
        }
        cp_wait0();
        GBAR(g);
    }

    float c = 0.f;

    for (int w = wfirst; w < end; w += RING) {
        int buf = (w >> 5) & 1;
        if (w != wfirst) {
            // prefetched buffer ready (issued a window ago); make visible,
            // kick prefetch for the window after next (pad covers overrun)
            cp_wait0();
            GBAR(g);
            if (lt < 64) {
                uint32_t dst = (uint32_t)__cvta_generic_to_shared(&xtile[g][buf ^ 1][lt * 4]);
                cp_async16(dst, &g_acc[(w + RING) * NO + lt * 4]);
                cp_commit();
            }
        }
        int nlo = (w < s0) ? s0 : w;
        int nhi = (w + RING < end) ? (w + RING) : end;
        const float* xbase = &xtile[g][buf][0];

        for (int n = nlo; n < nhi; n++) {
            int r = n & (RING - 1);
            const ulonglong2* xp = (const ulonglong2*)(xbase + r * NO);
            ulonglong2 xv0 = xp[0];
            ulonglong2 xv1 = xp[1];
            unsigned long long aA = pack2(bA, 0.f);
            unsigned long long aB = pack2(bB, 0.f);
            aA = fma2(xv0.x, wihA[0], aA); aB = fma2(xv0.x, wihB[0], aB);
            aA = fma2(xv0.y, wihA[1], aA); aB = fma2(xv0.y, wihB[1], aB);
            aA = fma2(xv1.x, wihA[2], aA); aB = fma2(xv1.x, wihB[2], aB);
            aA = fma2(xv1.y, wihA[3], aA); aB = fma2(xv1.y, wihB[3], aB);
            const ulonglong2* hp = (const ulonglong2*)hring[g][(n - 1) & (RING - 1)];
            #pragma unroll
            for (int k = 0; k < 16; k++) {
                ulonglong2 hv = hp[k];   // dual-broadcast LDS.128
                aA = fma2(hv.x, whhA[2 * k + 0], aA);
                aA = fma2(hv.y, whhA[2 * k + 1], aA);
                aB = fma2(hv.x, whhB[2 * k + 0], aB);
                aB = fma2(hv.y, whhB[2 * k + 1], aB);
            }
            float sA = unpack_sum(aA);
            float sB = unpack_sum(aB);
            float actA = fmaf(mA, tanh_a(sA * mA), kA);
            float actB = fmaf(0.5f, tanh_a(0.5f * sB), 0.5f);
            float rAv = __shfl_xor_sync(0xffffffffu, actA, 1);
            float rBv = __shfl_xor_sync(0xffffffffu, actB, 1);
            float iv = p ? rAv : actA;
            float fv = p ? rBv : actB;
            float gv = p ? actA : rAv;
            float ov = p ? actB : rBv;
            c = fmaf(fv, c, iv * gv);          // both lanes keep identical c
            float hn = ov * tanh_a(c);
            if (p == 0) hring[g][r][j] = hn;
            GBAR(g);
        }

        if (nhi > start) {
            // bulk output flush for [w, nhi) ∩ [start, end)
            // 4 threads per node: quarter q covers 16 of 64 hidden units
            int nn = w + (lt >> 2);
            int q = lt & 3;
            const float* hrow = hring[g][lt >> 2];
            float acc = 0.f;
            #pragma unroll
            for (int k = 0; k < 16; k++)
                acc = fmaf(hrow[q * 16 + k], swlin[q * 16 + k], acc);
            acc += __shfl_xor_sync(0xffffffffu, acc, 1);
            acc += __shfl_xor_sync(0xffffffffu, acc, 2);
            if (q == 0 && nn >= start && nn < nhi)
                out[nn] += acc;            // exclusive writer; out pre-set to wt
            // ring rows are rewritten only after the next window's barrier,
            // so no WAR hazard with this read.
        }
    }
}

// ---------------------------------------------------------------------------
extern "C" void kernel_launch(void* const* d_in, const int* in_sizes, int n_in,
                              void* d_out, int out_size) {
    const float* x        = (const float*)d_in[0];
    const int*   ei       = (const int*)  d_in[1];
    const float* weather  = (const float*)d_in[2];
    const float* timeenc  = (const float*)d_in[3];
    const float* W1rel    = (const float*)d_in[4];
    const float* b1       = (const float*)d_in[5];
    const float* W1root   = (const float*)d_in[6];
    const float* W2rel    = (const float*)d_in[7];
    const float* b2       = (const float*)d_in[8];
    const float* W2root   = (const float*)d_in[9];
    const float* Wih      = (const float*)d_in[10];
    const float* Whh      = (const float*)d_in[11];
    const float* bih      = (const float*)d_in[12];
    const float* bhh      = (const float*)d_in[13];
    const float* Wlin     = (const float*)d_in[14];
    const float* blin     = (const float*)d_in[15];
    float* out = (float*)d_out;

    prep_kernel<<<(N_NODES + 255) / 256, 256>>>(x, weather, timeenc, Wlin, blin, Wih, Whh);
    scatter1_kernel<<<(E_EDGES / 4 + 255) / 256, 256>>>(ei);
    node_kernel<<<(N_NODES + 255) / 256, 256>>>(W1rel, b1, W1root, W2rel, b2, W2root, out);
    scatter2_kernel<<<(E_EDGES + 255) / 256, 256>>>(ei);
    lstm_kernel<<<NBLK, 384>>>(Wih, Whh, bih, bhh, Wlin, out);
}

// round 10
// speedup vs baseline: 1.2786x; 1.0358x over previous
#include <cuda_runtime.h>
#include <cstdint>

#define N_NODES 64000
#define NPOINTS 2000
#define NB 32
#define TT 12
#define E_EDGES 1024000
#define GH 32
#define NO 8
#define HH 64
#define NBLK 148
#define NGROUPS 3
#define NCHUNKS (NBLK * NGROUPS)   // 444
#define CHUNK 145                  // ceil(64000/444)
#define LOOKBACK 12
#define RING 32

// scratch (static device globals; no allocation at runtime)
__device__ float g_x11[N_NODES];
__device__ float g_agg1[N_NODES];
__device__ float g_y[N_NODES * NO];
__device__ float g_acc[(N_NODES + 64) * NO];   // pad for staging/prefetch reads
__device__ float g_wt[NB];

// ---- packed f32x2 helpers -------------------------------------------------
__device__ __forceinline__ unsigned long long pack2(float lo, float hi) {
    unsigned long long r;
    asm("mov.b64 %0, {%1,%2};" : "=l"(r) : "f"(lo), "f"(hi));
    return r;
}
__device__ __forceinline__ unsigned long long fma2(unsigned long long a,
                                                   unsigned long long b,
                                                   unsigned long long c) {
    unsigned long long d;
    asm("fma.rn.f32x2 %0, %1, %2, %3;" : "=l"(d) : "l"(a), "l"(b), "l"(c));
    return d;
}
__device__ __forceinline__ float unpack_sum(unsigned long long v) {
    float lo, hi;
    asm("mov.b64 {%0,%1}, %2;" : "=f"(lo), "=f"(hi) : "l"(v));
    return lo + hi;
}
__device__ __forceinline__ float tanh_a(float x) {
    float y;
    asm("tanh.approx.f32 %0, %1;" : "=f"(y) : "f"(x));
    return y;
}
__device__ __forceinline__ void cp_async16(uint32_t smem_addr, const void* gptr) {
    asm volatile("cp.async.cg.shared.global [%0], [%1], 16;"
                 :: "r"(smem_addr), "l"(gptr) : "memory");
}
__device__ __forceinline__ void cp_commit() {
    asm volatile("cp.async.commit_group;" ::: "memory");
}
__device__ __forceinline__ void cp_wait0() {
    asm volatile("cp.async.wait_group 0;" ::: "memory");
}
__device__ __forceinline__ void prefetch_l2(const void* p) {
    asm volatile("prefetch.global.L2 [%0];" :: "l"(p));
}

// ---------------------------------------------------------------------------
// K1: extract x at t=11, zero agg1, weather/time scalar, prefetch LSTM weights
// ---------------------------------------------------------------------------
__global__ void prep_kernel(const float* __restrict__ x,
                            const float* __restrict__ weather,
                            const float* __restrict__ timeenc,
                            const float* __restrict__ Wlin,
                            const float* __restrict__ blin,
                            const float* __restrict__ Wih,
                            const float* __restrict__ Whh) {
    int n = blockIdx.x * blockDim.x + threadIdx.x;
    if (n < N_NODES) {
        int b = n / NPOINTS;
        int p = n - b * NPOINTS;
        g_x11[n] = x[b * (TT * NPOINTS) + 11 * NPOINTS + p];
        g_agg1[n] = 0.f;
    }
    // warm L2 with LSTM weights (Whh 64KB, Wih 8KB)
    if (n < 512) prefetch_l2((const char*)Whh + n * 128);
    else if (n < 576) prefetch_l2((const char*)Wih + (n - 512) * 128);
    if (blockIdx.x == 0 && threadIdx.x < NB) {
        int b = threadIdx.x;
        float s = __ldg(&blin[0]);
        #pragma unroll
        for (int j = 0; j < 4; j++)
            s += weather[b * TT * 4 + 11 * 4 + j] * Wlin[64 + j];
        #pragma unroll
        for (int j = 0; j < 8; j++)
            s += timeenc[b * TT * 8 + 11 * 8 + j] * Wlin[68 + j];
        g_wt[b] = s;
    }
}

// ---------------------------------------------------------------------------
// K2: agg1[dst] += x11[src]
// ---------------------------------------------------------------------------
__global__ void scatter1_kernel(const int* __restrict__ ei) {
    int i = blockIdx.x * blockDim.x + threadIdx.x;
    if (i * 4 >= E_EDGES) return;
    int4 s4 = ((const int4*)ei)[i];
    int4 d4 = ((const int4*)(ei + E_EDGES))[i];
    atomicAdd(&g_agg1[d4.x], __ldg(&g_x11[s4.x]));
    atomicAdd(&g_agg1[d4.y], __ldg(&g_x11[s4.y]));
    atomicAdd(&g_agg1[d4.z], __ldg(&g_x11[s4.z]));
    atomicAdd(&g_agg1[d4.w], __ldg(&g_x11[s4.w]));
}

// ---------------------------------------------------------------------------
// K3: node MLP; writes y (edge payload), acc (root part), out init (= wt)
// ---------------------------------------------------------------------------
__global__ void node_kernel(const float* __restrict__ W1rel,
                            const float* __restrict__ b1,
                            const float* __restrict__ W1root,
                            const float* __restrict__ W2rel,
                            const float* __restrict__ b2,
                            const float* __restrict__ W2root,
                            float* __restrict__ out) {
    __shared__ float sW1rel[GH], sb1[GH], sW1root[GH];
    __shared__ float sW2rel[GH * NO], sW2root[GH * NO], sb2[NO];
    int tid = threadIdx.x;
    if (tid < GH) {
        sW1rel[tid] = W1rel[tid];
        sb1[tid] = b1[tid];
        sW1root[tid] = W1root[tid];
    }
    if (tid < GH * NO) {
        sW2rel[tid] = W2rel[tid];
        sW2root[tid] = W2root[tid];
    }
    if (tid < NO) sb2[tid] = b2[tid];
    __syncthreads();

    int n = blockIdx.x * blockDim.x + tid;
    if (n >= N_NODES) return;
    float a = g_agg1[n];
    float xv = g_x11[n];
    float y[NO], p[NO];
    #pragma unroll
    for (int j = 0; j < NO; j++) { y[j] = 0.f; p[j] = sb2[j]; }
    #pragma unroll
    for (int k = 0; k < GH; k++) {
        float h1 = fmaf(a, sW1rel[k], fmaf(xv, sW1root[k], sb1[k]));
        h1 = fmaxf(h1, 0.f);
        #pragma unroll
        for (int j = 0; j < NO; j++) {
            y[j] = fmaf(h1, sW2rel[k * NO + j], y[j]);
            p[j] = fmaf(h1, sW2root[k * NO + j], p[j]);
        }
    }
    float4* yp = (float4*)&g_y[n * NO];
    yp[0] = make_float4(y[0], y[1], y[2], y[3]);
    yp[1] = make_float4(y[4], y[5], y[6], y[7]);
    float4* ap = (float4*)&g_acc[n * NO];
    ap[0] = make_float4(p[0], p[1], p[2], p[3]);
    ap[1] = make_float4(p[4], p[5], p[6], p[7]);
    out[n] = g_wt[n & (NB - 1)];
}

// ---------------------------------------------------------------------------
// K4: acc[dst] += y[src]   (8 floats/edge, vector reductions)
// ---------------------------------------------------------------------------
__device__ __forceinline__ void red_add_v4(float* addr, float4 v) {
    asm volatile("red.global.add.v4.f32 [%0], {%1,%2,%3,%4};"
                 :: "l"(addr), "f"(v.x), "f"(v.y), "f"(v.z), "f"(v.w)
                 : "memory");
}

__global__ void scatter2_kernel(const int* __restrict__ ei) {
    int e = blockIdx.x * blockDim.x + threadIdx.x;
    if (e >= E_EDGES) return;
    int s = __ldg(&ei[e]);
    int d = __ldg(&ei[E_EDGES + e]);
    const float4* yp = (const float4*)&g_y[s * NO];
    float4 va = __ldg(yp);
    float4 vb = __ldg(yp + 1);
    red_add_v4(&g_acc[d * NO], va);
    red_add_v4(&g_acc[d * NO + 4], vb);
}

// ---------------------------------------------------------------------------
// K5: LSTM scan. 3 independent chains per block (named-barrier groups of
// 4 warps / 128 threads). Window-nested loop. Lane roles are symmetric:
// lane p=0 of a pair holds gates (i,f), lane p=1 holds (g,o); after one
// shfl_xor the p=0 lane combines own (i,f) with partner (g,o) directly —
// no operand selection. p=1 lanes carry a garbage c that is never read.
// ---------------------------------------------------------------------------
#define GBAR(gid) asm volatile("bar.sync %0, 128;" :: "r"((gid) + 1) : "memory")

__global__ void __launch_bounds__(384, 1) lstm_kernel(
    const float* __restrict__ Wih, const float* __restrict__ Whh,
    const float* __restrict__ bih, const float* __restrict__ bhh,
    const float* __restrict__ Wlin, float* __restrict__ out) {
    __shared__ __align__(16) float hring[NGROUPS][RING][68];
    __shared__ __align__(16) float xtile[NGROUPS][2][RING * NO];
    __shared__ float swlin[HH];

    int tid = threadIdx.x;
    int g = tid >> 7;            // group 0..2
    int lt = tid & 127;          // thread within group
    int l = tid & 31;
    int wl = (tid >> 5) & 3;     // warp within group
    int j = wl * 16 + (l >> 1);  // hidden unit
    int p = l & 1;               // gate-pair selector
    int gidxA = (2 * p) * 64 + j;        // p=0: i ; p=1: g
    int gidxB = gidxA + 64;              // p=0: f ; p=1: o

    // packed weights over the reduction dim (64 ull = 128 regs, L2-hot)
    unsigned long long whhA[HH / 2], whhB[HH / 2];
    #pragma unroll
    for (int k = 0; k < HH / 2; k++) {
        whhA[k] = pack2(__ldg(&Whh[(2 * k) * 256 + gidxA]),
                        __ldg(&Whh[(2 * k + 1) * 256 + gidxA]));
        whhB[k] = pack2(__ldg(&Whh[(2 * k) * 256 + gidxB]),
                        __ldg(&Whh[(2 * k + 1) * 256 + gidxB]));
    }
    unsigned long long wihA[NO / 2], wihB[NO / 2];
    #pragma unroll
    for (int k = 0; k < NO / 2; k++) {
        wihA[k] = pack2(__ldg(&Wih[(2 * k) * 256 + gidxA]),
                        __ldg(&Wih[(2 * k + 1) * 256 + gidxA]));
        wihB[k] = pack2(__ldg(&Wih[(2 * k) * 256 + gidxB]),
                        __ldg(&Wih[(2 * k + 1) * 256 + gidxB]));
    }
    // hoisted packed biases (saves per-step movs)
    unsigned long long bA2 = pack2(__ldg(&bih[gidxA]) + __ldg(&bhh[gidxA]), 0.f);
    unsigned long long bB2 = pack2(__ldg(&bih[gidxB]) + __ldg(&bhh[gidxB]), 0.f);
    // activation constants: actA = fma(mA, tanh(sA*mA), kA)
    float mA = p ? 1.f : 0.5f;   // p=0: sigmoid(i)/(f) ; p=1: tanh(g), sigmoid(o)
    float kA = p ? 0.f : 0.5f;

    for (int k = lt; k < RING * 68; k += 128)
        ((float*)hring[g])[k] = 0.f;
    if (tid < HH) swlin[tid] = __ldg(&Wlin[tid]);
    __syncthreads();   // whole block once; groups independent afterwards

    int chunk = blockIdx.x * NGROUPS + g;
    int start = chunk * CHUNK;
    if (start >= N_NODES) return;   // whole group exits uniformly
    int end = start + CHUNK;
    if (end > N_NODES) end = N_NODES;
    int s0 = start - LOOKBACK;
    if (s0 < 0) s0 = 0;
    int wfirst = s0 & ~(RING - 1);

    // prime double-buffered x staging: windows wfirst and wfirst+RING
    {
        int b0 = (wfirst >> 5) & 1;
        if (lt < 64) {
            uint32_t dst0 = (uint32_t)__cvta_generic_to_shared(&xtile[g][b0][lt * 4]);
            cp_async16(dst0, &g_acc[wfirst * NO + lt * 4]);
            cp_commit();
            uint32_t dst1 = (uint32_t)__cvta_generic_to_shared(&xtile[g][b0 ^ 1][lt * 4]);
            cp_async16(dst1, &g_acc[(wfirst + RING) * NO + lt * 4]);
            cp_commit();
        }
        cp_wait0();
        GBAR(g);
    }

    float c = 0.f;

    for (int w = wfirst; w < end; w += RING) {
        int buf = (w >> 5) & 1;
        if (w != wfirst) {
            // prefetched buffer ready (issued a window ago); make visible,
            // kick prefetch for the window after next (pad covers overrun)
            cp_wait0();
            GBAR(g);
            if (lt < 64) {
                uint32_t dst = (uint32_t)__cvta_generic_to_shared(&xtile[g][buf ^ 1][lt * 4]);
                cp_async16(dst, &g_acc[(w + RING) * NO + lt * 4]);
                cp_commit();
            }
        }
        int nlo = (w < s0) ? s0 : w;
        int nhi = (w + RING < end) ? (w + RING) : end;
        const float* xbase = &xtile[g][buf][0];

        for (int n = nlo; n < nhi; n++) {
            int r = n & (RING - 1);
            const ulonglong2* xp = (const ulonglong2*)(xbase + r * NO);
            ulonglong2 xv0 = xp[0];
            ulonglong2 xv1 = xp[1];
            unsigned long long aA = bA2;
            unsigned long long aB = bB2;
            aA = fma2(xv0.x, wihA[0], aA); aB = fma2(xv0.x, wihB[0], aB);
            aA = fma2(xv0.y, wihA[1], aA); aB = fma2(xv0.y, wihB[1], aB);
            aA = fma2(xv1.x, wihA[2], aA); aB = fma2(xv1.x, wihB[2], aB);
            aA = fma2(xv1.y, wihA[3], aA); aB = fma2(xv1.y, wihB[3], aB);
            const ulonglong2* hp = (const ulonglong2*)hring[g][(n - 1) & (RING - 1)];
            #pragma unroll
            for (int k = 0; k < 16; k++) {
                ulonglong2 hv = hp[k];   // dual-broadcast LDS.128
                aA = fma2(hv.x, whhA[2 * k + 0], aA);
                aA = fma2(hv.y, whhA[2 * k + 1], aA);
                aB = fma2(hv.x, whhB[2 * k + 0], aB);
                aB = fma2(hv.y, whhB[2 * k + 1], aB);
            }
            float sA = unpack_sum(aA);
            float sB = unpack_sum(aB);
            // p=0: actA=sigmoid(i), actB=sigmoid(f) ; p=1: actA=tanh(g), actB=sigmoid(o)
            float actA = fmaf(mA, tanh_a(sA * mA), kA);
            float actB = fmaf(0.5f, tanh_a(0.5f * sB), 0.5f);
            float rAv = __shfl_xor_sync(0xffffffffu, actA, 1);   // p=0 gets tanh(g)
            float rBv = __shfl_xor_sync(0xffffffffu, actB, 1);   // p=0 gets sigmoid(o)
            // valid on p=0 lanes only: c = f*c + i*g ; hn = o*tanh(c)
            // (p=1 lanes compute a garbage c that is never stored or read)
            c = fmaf(actB, c, actA * rAv);
            float hn = rBv * tanh_a(c);
            if (p == 0) hring[g][r][j] = hn;
            GBAR(g);
        }

        if (nhi > start) {
            // bulk output flush for [w, nhi) ∩ [start, end)
            // 4 threads per node: quarter q covers 16 of 64 hidden units
            int nn = w + (lt >> 2);
            int q = lt & 3;
            const float* hrow = hring[g][lt >> 2];
            float acc = 0.f;
            #pragma unroll
            for (int k = 0; k < 16; k++)
                acc = fmaf(hrow[q * 16 + k], swlin[q * 16 + k], acc);
            acc += __shfl_xor_sync(0xffffffffu, acc, 1);
            acc += __shfl_xor_sync(0xffffffffu, acc, 2);
            if (q == 0 && nn >= start && nn < nhi)
                out[nn] += acc;            // exclusive writer; out pre-set to wt
            // ring rows are rewritten only after the next window's barrier,
            // so no WAR hazard with this read.
        }
    }
}

// ---------------------------------------------------------------------------
extern "C" void kernel_launch(void* const* d_in, const int* in_sizes, int n_in,
                              void* d_out, int out_size) {
    const float* x        = (const float*)d_in[0];
    const int*   ei       = (const int*)  d_in[1];
    const float* weather  = (const float*)d_in[2];
    const float* timeenc  = (const float*)d_in[3];
    const float* W1rel    = (const float*)d_in[4];
    const float* b1       = (const float*)d_in[5];
    const float* W1root   = (const float*)d_in[6];
    const float* W2rel    = (const float*)d_in[7];
    const float* b2       = (const float*)d_in[8];
    const float* W2root   = (const float*)d_in[9];
    const float* Wih      = (const float*)d_in[10];
    const float* Whh      = (const float*)d_in[11];
    const float* bih      = (const float*)d_in[12];
    const float* bhh      = (const float*)d_in[13];
    const float* Wlin     = (const float*)d_in[14];
    const float* blin     = (const float*)d_in[15];
    float* out = (float*)d_out;

    prep_kernel<<<(N_NODES + 255) / 256, 256>>>(x, weather, timeenc, Wlin, blin, Wih, Whh);
    scatter1_kernel<<<(E_EDGES / 4 + 255) / 256, 256>>>(ei);
    node_kernel<<<(N_NODES + 255) / 256, 256>>>(W1rel, b1, W1root, W2rel, b2, W2root, out);
    scatter2_kernel<<<(E_EDGES + 255) / 256, 256>>>(ei);
    lstm_kernel<<<NBLK, 384>>>(Wih, Whh, bih, bhh, Wlin, out);
}

// round 11
// speedup vs baseline: 1.2972x; 1.0145x over previous
#include <cuda_runtime.h>
#include <cstdint>

#define N_NODES 64000
#define NPOINTS 2000
#define NB 32
#define TT 12
#define E_EDGES 1024000
#define GH 32
#define NO 8
#define HH 64
#define NBLK 148
#define NGROUPS 3
#define NCHUNKS (NBLK * NGROUPS)   // 444
#define CHUNK 145                  // ceil(64000/444)
#define LOOKBACK 12
#define RING 32

// scratch (static device globals; no allocation at runtime)
__device__ float g_x11[N_NODES];
__device__ float g_agg1[N_NODES];
__device__ float g_y[N_NODES * NO];
__device__ float g_acc[(N_NODES + 64) * NO];   // pad for staging/prefetch reads
__device__ float g_wt[NB];

// ---- packed f32x2 helpers -------------------------------------------------
__device__ __forceinline__ unsigned long long pack2(float lo, float hi) {
    unsigned long long r;
    asm("mov.b64 %0, {%1,%2};" : "=l"(r) : "f"(lo), "f"(hi));
    return r;
}
__device__ __forceinline__ unsigned long long fma2(unsigned long long a,
                                                   unsigned long long b,
                                                   unsigned long long c) {
    unsigned long long d;
    asm("fma.rn.f32x2 %0, %1, %2, %3;" : "=l"(d) : "l"(a), "l"(b), "l"(c));
    return d;
}
__device__ __forceinline__ float unpack_sum(unsigned long long v) {
    float lo, hi;
    asm("mov.b64 {%0,%1}, %2;" : "=f"(lo), "=f"(hi) : "l"(v));
    return lo + hi;
}
__device__ __forceinline__ float tanh_a(float x) {
    float y;
    asm("tanh.approx.f32 %0, %1;" : "=f"(y) : "f"(x));
    return y;
}
__device__ __forceinline__ void cp_async16(uint32_t smem_addr, const void* gptr) {
    asm volatile("cp.async.cg.shared.global [%0], [%1], 16;"
                 :: "r"(smem_addr), "l"(gptr) : "memory");
}
__device__ __forceinline__ void cp_commit() {
    asm volatile("cp.async.commit_group;" ::: "memory");
}
__device__ __forceinline__ void cp_wait0() {
    asm volatile("cp.async.wait_group 0;" ::: "memory");
}
__device__ __forceinline__ void prefetch_l2(const void* p) {
    asm volatile("prefetch.global.L2 [%0];" :: "l"(p));
}
// ---- programmatic dependent launch ----------------------------------------
__device__ __forceinline__ void gdc_launch() {
    asm volatile("griddepcontrol.launch_dependents;" ::: "memory");
}
__device__ __forceinline__ void gdc_wait() {
    asm volatile("griddepcontrol.wait;" ::: "memory");
}

// ---------------------------------------------------------------------------
// K1: extract x at t=11, zero agg1, weather/time scalar, prefetch LSTM weights
// ---------------------------------------------------------------------------
__global__ void prep_kernel(const float* __restrict__ x,
                            const float* __restrict__ weather,
                            const float* __restrict__ timeenc,
                            const float* __restrict__ Wlin,
                            const float* __restrict__ blin,
                            const float* __restrict__ Wih,
                            const float* __restrict__ Whh) {
    gdc_launch();
    int n = blockIdx.x * blockDim.x + threadIdx.x;
    if (n < N_NODES) {
        int b = n / NPOINTS;
        int p = n - b * NPOINTS;
        g_x11[n] = x[b * (TT * NPOINTS) + 11 * NPOINTS + p];
        g_agg1[n] = 0.f;
    }
    // warm L2 with LSTM weights (Whh 64KB, Wih 8KB)
    if (n < 512) prefetch_l2((const char*)Whh + n * 128);
    else if (n < 576) prefetch_l2((const char*)Wih + (n - 512) * 128);
    if (blockIdx.x == 0 && threadIdx.x < NB) {
        int b = threadIdx.x;
        float s = __ldg(&blin[0]);
        #pragma unroll
        for (int j = 0; j < 4; j++)
            s += weather[b * TT * 4 + 11 * 4 + j] * Wlin[64 + j];
        #pragma unroll
        for (int j = 0; j < 8; j++)
            s += timeenc[b * TT * 8 + 11 * 8 + j] * Wlin[68 + j];
        g_wt[b] = s;
    }
}

// ---------------------------------------------------------------------------
// K2: agg1[dst] += x11[src]. Index loads (external input) overlap with prep
// via PDL; gdc_wait before touching g_x11/g_agg1.
// ---------------------------------------------------------------------------
__global__ void scatter1_kernel(const int* __restrict__ ei) {
    gdc_launch();
    int i = blockIdx.x * blockDim.x + threadIdx.x;
    if (i * 4 >= E_EDGES) { gdc_wait(); return; }
    int4 s4 = ((const int4*)ei)[i];
    int4 d4 = ((const int4*)(ei + E_EDGES))[i];
    gdc_wait();
    atomicAdd(&g_agg1[d4.x], __ldg(&g_x11[s4.x]));
    atomicAdd(&g_agg1[d4.y], __ldg(&g_x11[s4.y]));
    atomicAdd(&g_agg1[d4.z], __ldg(&g_x11[s4.z]));
    atomicAdd(&g_agg1[d4.w], __ldg(&g_x11[s4.w]));
}

// ---------------------------------------------------------------------------
// K3: node MLP; smem weight fill (external inputs) overlaps with scatter1.
// ---------------------------------------------------------------------------
__global__ void node_kernel(const float* __restrict__ W1rel,
                            const float* __restrict__ b1,
                            const float* __restrict__ W1root,
                            const float* __restrict__ W2rel,
                            const float* __restrict__ b2,
                            const float* __restrict__ W2root,
                            float* __restrict__ out) {
    gdc_launch();
    __shared__ float sW1rel[GH], sb1[GH], sW1root[GH];
    __shared__ float sW2rel[GH * NO], sW2root[GH * NO], sb2[NO];
    int tid = threadIdx.x;
    if (tid < GH) {
        sW1rel[tid] = W1rel[tid];
        sb1[tid] = b1[tid];
        sW1root[tid] = W1root[tid];
    }
    if (tid < GH * NO) {
        sW2rel[tid] = W2rel[tid];
        sW2root[tid] = W2root[tid];
    }
    if (tid < NO) sb2[tid] = b2[tid];
    __syncthreads();
    gdc_wait();

    int n = blockIdx.x * blockDim.x + tid;
    if (n >= N_NODES) return;
    float a = g_agg1[n];
    float xv = g_x11[n];
    float y[NO], p[NO];
    #pragma unroll
    for (int j = 0; j < NO; j++) { y[j] = 0.f; p[j] = sb2[j]; }
    #pragma unroll
    for (int k = 0; k < GH; k++) {
        float h1 = fmaf(a, sW1rel[k], fmaf(xv, sW1root[k], sb1[k]));
        h1 = fmaxf(h1, 0.f);
        #pragma unroll
        for (int j = 0; j < NO; j++) {
            y[j] = fmaf(h1, sW2rel[k * NO + j], y[j]);
            p[j] = fmaf(h1, sW2root[k * NO + j], p[j]);
        }
    }
    float4* yp = (float4*)&g_y[n * NO];
    yp[0] = make_float4(y[0], y[1], y[2], y[3]);
    yp[1] = make_float4(y[4], y[5], y[6], y[7]);
    float4* ap = (float4*)&g_acc[n * NO];
    ap[0] = make_float4(p[0], p[1], p[2], p[3]);
    ap[1] = make_float4(p[4], p[5], p[6], p[7]);
    out[n] = g_wt[n & (NB - 1)];
}

// ---------------------------------------------------------------------------
// K4: acc[dst] += y[src]   (8 floats/edge, vector reductions)
// ---------------------------------------------------------------------------
__device__ __forceinline__ void red_add_v4(float* addr, float4 v) {
    asm volatile("red.global.add.v4.f32 [%0], {%1,%2,%3,%4};"
                 :: "l"(addr), "f"(v.x), "f"(v.y), "f"(v.z), "f"(v.w)
                 : "memory");
}

__global__ void scatter2_kernel(const int* __restrict__ ei) {
    gdc_launch();
    int e = blockIdx.x * blockDim.x + threadIdx.x;
    if (e >= E_EDGES) { gdc_wait(); return; }
    int s = __ldg(&ei[e]);
    int d = __ldg(&ei[E_EDGES + e]);
    gdc_wait();
    const float4* yp = (const float4*)&g_y[s * NO];
    float4 va = __ldg(yp);
    float4 vb = __ldg(yp + 1);
    red_add_v4(&g_acc[d * NO], va);
    red_add_v4(&g_acc[d * NO + 4], vb);
}

// ---------------------------------------------------------------------------
// K5: LSTM scan. 3 independent chains per block (named-barrier groups of
// 4 warps / 128 threads). Weight register preload + ring zero + swlin fill
// run BEFORE gdc_wait (overlapped with scatter2 via PDL).
// ---------------------------------------------------------------------------
#define GBAR(gid) asm volatile("bar.sync %0, 128;" :: "r"((gid) + 1) : "memory")

__global__ void __launch_bounds__(384, 1) lstm_kernel(
    const float* __restrict__ Wih, const float* __restrict__ Whh,
    const float* __restrict__ bih, const float* __restrict__ bhh,
    const float* __restrict__ Wlin, float* __restrict__ out) {
    __shared__ __align__(16) float hring[NGROUPS][RING][68];
    __shared__ __align__(16) float xtile[NGROUPS][2][RING * NO];
    __shared__ float swlin[HH];

    int tid = threadIdx.x;
    int g = tid >> 7;            // group 0..2
    int lt = tid & 127;          // thread within group
    int l = tid & 31;
    int wl = (tid >> 5) & 3;     // warp within group
    int j = wl * 16 + (l >> 1);  // hidden unit
    int p = l & 1;               // gate-pair selector
    int gidxA = (2 * p) * 64 + j;        // p=0: i ; p=1: g
    int gidxB = gidxA + 64;              // p=0: f ; p=1: o

    // packed weights over the reduction dim (64 ull = 128 regs, L2-hot;
    // overlapped with scatter2 execution via PDL)
    unsigned long long whhA[HH / 2], whhB[HH / 2];
    #pragma unroll
    for (int k = 0; k < HH / 2; k++) {
        whhA[k] = pack2(__ldg(&Whh[(2 * k) * 256 + gidxA]),
                        __ldg(&Whh[(2 * k + 1) * 256 + gidxA]));
        whhB[k] = pack2(__ldg(&Whh[(2 * k) * 256 + gidxB]),
                        __ldg(&Whh[(2 * k + 1) * 256 + gidxB]));
    }
    unsigned long long wihA[NO / 2], wihB[NO / 2];
    #pragma unroll
    for (int k = 0; k < NO / 2; k++) {
        wihA[k] = pack2(__ldg(&Wih[(2 * k) * 256 + gidxA]),
                        __ldg(&Wih[(2 * k + 1) * 256 + gidxA]));
        wihB[k] = pack2(__ldg(&Wih[(2 * k) * 256 + gidxB]),
                        __ldg(&Wih[(2 * k + 1) * 256 + gidxB]));
    }
    // hoisted packed biases
    unsigned long long bA2 = pack2(__ldg(&bih[gidxA]) + __ldg(&bhh[gidxA]), 0.f);
    unsigned long long bB2 = pack2(__ldg(&bih[gidxB]) + __ldg(&bhh[gidxB]), 0.f);
    // activation constants: actA = fma(mA, tanh(sA*mA), kA)
    float mA = p ? 1.f : 0.5f;   // p=0: sigmoid(i)/(f) ; p=1: tanh(g), sigmoid(o)
    float kA = p ? 0.f : 0.5f;

    for (int k = lt; k < RING * 68; k += 128)
        ((float*)hring[g])[k] = 0.f;
    if (tid < HH) swlin[tid] = __ldg(&Wlin[tid]);
    __syncthreads();   // whole block once; groups independent afterwards

    int chunk = blockIdx.x * NGROUPS + g;
    int start = chunk * CHUNK;
    int end = start + CHUNK;
    if (end > N_NODES) end = N_NODES;
    int s0 = start - LOOKBACK;
    if (s0 < 0) s0 = 0;
    int wfirst = s0 & ~(RING - 1);

    gdc_wait();   // g_acc / out ready (scatter2 + node complete)
    if (start >= N_NODES) return;   // whole group exits uniformly

    // prime double-buffered x staging: windows wfirst and wfirst+RING
    {
        int b0 = (wfirst >> 5) & 1;
        if (lt < 64) {
            uint32_t dst0 = (uint32_t)__cvta_generic_to_shared(&xtile[g][b0][lt * 4]);
            cp_async16(dst0, &g_acc[wfirst * NO + lt * 4]);
            cp_commit();
            uint32_t dst1 = (uint32_t)__cvta_generic_to_shared(&xtile[g][b0 ^ 1][lt * 4]);
            cp_async16(dst1, &g_acc[(wfirst + RING) * NO + lt * 4]);
            cp_commit();
        }
        cp_wait0();
        GBAR(g);
    }

    float c = 0.f;

    for (int w = wfirst; w < end; w += RING) {
        int buf = (w >> 5) & 1;
        if (w != wfirst) {
            // prefetched buffer ready (issued a window ago); make visible,
            // kick prefetch for the window after next (pad covers overrun)
            cp_wait0();
            GBAR(g);
            if (lt < 64) {
                uint32_t dst = (uint32_t)__cvta_generic_to_shared(&xtile[g][buf ^ 1][lt * 4]);
                cp_async16(dst, &g_acc[(w + RING) * NO + lt * 4]);
                cp_commit();
            }
        }
        int nlo = (w < s0) ? s0 : w;
        int nhi = (w + RING < end) ? (w + RING) : end;
        const float* xbase = &xtile[g][buf][0];

        for (int n = nlo; n < nhi; n++) {
            int r = n & (RING - 1);
            const ulonglong2* xp = (const ulonglong2*)(xbase + r * NO);
            ulonglong2 xv0 = xp[0];
            ulonglong2 xv1 = xp[1];
            unsigned long long aA = bA2;
            unsigned long long aB = bB2;
            aA = fma2(xv0.x, wihA[0], aA); aB = fma2(xv0.x, wihB[0], aB);
            aA = fma2(xv0.y, wihA[1], aA); aB = fma2(xv0.y, wihB[1], aB);
            aA = fma2(xv1.x, wihA[2], aA); aB = fma2(xv1.x, wihB[2], aB);
            aA = fma2(xv1.y, wihA[3], aA); aB = fma2(xv1.y, wihB[3], aB);
            const ulonglong2* hp = (const ulonglong2*)hring[g][(n - 1) & (RING - 1)];
            #pragma unroll
            for (int k = 0; k < 16; k++) {
                ulonglong2 hv = hp[k];   // dual-broadcast LDS.128
                aA = fma2(hv.x, whhA[2 * k + 0], aA);
                aA = fma2(hv.y, whhA[2 * k + 1], aA);
                aB = fma2(hv.x, whhB[2 * k + 0], aB);
                aB = fma2(hv.y, whhB[2 * k + 1], aB);
            }
            float sA = unpack_sum(aA);
            float sB = unpack_sum(aB);
            // p=0: actA=sigmoid(i), actB=sigmoid(f) ; p=1: actA=tanh(g), actB=sigmoid(o)
            float actA = fmaf(mA, tanh_a(sA * mA), kA);
            float actB = fmaf(0.5f, tanh_a(0.5f * sB), 0.5f);
            float rAv = __shfl_xor_sync(0xffffffffu, actA, 1);   // p=0 gets tanh(g)
            float rBv = __shfl_xor_sync(0xffffffffu, actB, 1);   // p=0 gets sigmoid(o)
            // valid on p=0 lanes only: c = f*c + i*g ; hn = o*tanh(c)
            c = fmaf(actB, c, actA * rAv);
            float hn = rBv * tanh_a(c);
            if (p == 0) hring[g][r][j] = hn;
            GBAR(g);
        }

        if (nhi > start) {
            // bulk output flush for [w, nhi) ∩ [start, end)
            int nn = w + (lt >> 2);
            int q = lt & 3;
            const float* hrow = hring[g][lt >> 2];
            float acc = 0.f;
            #pragma unroll
            for (int k = 0; k < 16; k++)
                acc = fmaf(hrow[q * 16 + k], swlin[q * 16 + k], acc);
            acc += __shfl_xor_sync(0xffffffffu, acc, 1);
            acc += __shfl_xor_sync(0xffffffffu, acc, 2);
            if (q == 0 && nn >= start && nn < nhi)
                out[nn] += acc;            // exclusive writer; out pre-set to wt
        }
    }
}

// ---------------------------------------------------------------------------
template <typename... Args>
static inline void launch_pdl(void (*kern)(Args...), dim3 grid, dim3 block,
                              Args... args) {
    cudaLaunchConfig_t cfg = {};
    cfg.gridDim = grid;
    cfg.blockDim = block;
    cfg.dynamicSmemBytes = 0;
    cfg.stream = 0;
    cudaLaunchAttribute attr[1];
    attr[0].id = cudaLaunchAttributeProgrammaticStreamSerialization;
    attr[0].val.programmaticStreamSerializationAllowed = 1;
    cfg.attrs = attr;
    cfg.numAttrs = 1;
    cudaLaunchKernelEx(&cfg, kern, args...);
}

extern "C" void kernel_launch(void* const* d_in, const int* in_sizes, int n_in,
                              void* d_out, int out_size) {
    const float* x        = (const float*)d_in[0];
    const int*   ei       = (const int*)  d_in[1];
    const float* weather  = (const float*)d_in[2];
    const float* timeenc  = (const float*)d_in[3];
    const float* W1rel    = (const float*)d_in[4];
    const float* b1       = (const float*)d_in[5];
    const float* W1root   = (const float*)d_in[6];
    const float* W2rel    = (const float*)d_in[7];
    const float* b2       = (const float*)d_in[8];
    const float* W2root   = (const float*)d_in[9];
    const float* Wih      = (const float*)d_in[10];
    const float* Whh      = (const float*)d_in[11];
    const float* bih      = (const float*)d_in[12];
    const float* bhh      = (const float*)d_in[13];
    const float* Wlin     = (const float*)d_in[14];
    const float* blin     = (const float*)d_in[15];
    float* out = (float*)d_out;

    prep_kernel<<<(N_NODES + 255) / 256, 256>>>(x, weather, timeenc, Wlin, blin, Wih, Whh);
    launch_pdl(scatter1_kernel, dim3((E_EDGES / 4 + 255) / 256), dim3(256), ei);
    launch_pdl(node_kernel, dim3((N_NODES + 255) / 256), dim3(256),
               W1rel, b1, W1root, W2rel, b2, W2root, out);
    launch_pdl(scatter2_kernel, dim3((E_EDGES + 255) / 256), dim3(256), ei);
    launch_pdl(lstm_kernel, dim3(NBLK), dim3(384), Wih, Whh, bih, bhh, Wlin, out);
}

// round 12
// speedup vs baseline: 1.3017x; 1.0035x over previous
#include <cuda_runtime.h>
#include <cstdint>

#define N_NODES 64000
#define NPOINTS 2000
#define NB 32
#define TT 12
#define E_EDGES 1024000
#define GH 32
#define NO 8
#define HH 64
#define NBLK 148
#define NGROUPS 3
#define NCHUNKS (NBLK * NGROUPS)   // 444
#define CHUNK 145                  // ceil(64000/444)
#define LOOKBACK 12
#define RING 32

// scratch (static device globals; zero-initialized at module load)
__device__ float g_agg1[N_NODES];            // re-zeroed by node_kernel each run
__device__ float g_y[N_NODES * NO];
__device__ float g_acc[(N_NODES + 64) * NO]; // pad for staging/prefetch reads

// ---- packed f32x2 helpers -------------------------------------------------
__device__ __forceinline__ unsigned long long pack2(float lo, float hi) {
    unsigned long long r;
    asm("mov.b64 %0, {%1,%2};" : "=l"(r) : "f"(lo), "f"(hi));
    return r;
}
__device__ __forceinline__ unsigned long long fma2(unsigned long long a,
                                                   unsigned long long b,
                                                   unsigned long long c) {
    unsigned long long d;
    asm("fma.rn.f32x2 %0, %1, %2, %3;" : "=l"(d) : "l"(a), "l"(b), "l"(c));
    return d;
}
__device__ __forceinline__ float unpack_sum(unsigned long long v) {
    float lo, hi;
    asm("mov.b64 {%0,%1}, %2;" : "=f"(lo), "=f"(hi) : "l"(v));
    return lo + hi;
}
__device__ __forceinline__ float tanh_a(float x) {
    float y;
    asm("tanh.approx.f32 %0, %1;" : "=f"(y) : "f"(x));
    return y;
}
__device__ __forceinline__ void cp_async16(uint32_t smem_addr, const void* gptr) {
    asm volatile("cp.async.cg.shared.global [%0], [%1], 16;"
                 :: "r"(smem_addr), "l"(gptr) : "memory");
}
__device__ __forceinline__ void cp_commit() {
    asm volatile("cp.async.commit_group;" ::: "memory");
}
__device__ __forceinline__ void cp_wait0() {
    asm volatile("cp.async.wait_group 0;" ::: "memory");
}
__device__ __forceinline__ void prefetch_l2(const void* p) {
    asm volatile("prefetch.global.L2 [%0];" :: "l"(p));
}
// ---- programmatic dependent launch ----------------------------------------
__device__ __forceinline__ void gdc_launch() {
    asm volatile("griddepcontrol.launch_dependents;" ::: "memory");
}
__device__ __forceinline__ void gdc_wait() {
    asm volatile("griddepcontrol.wait;" ::: "memory");
}

// x[b][11][p] address for node n = b*NPOINTS + p
__device__ __forceinline__ int x11_index(int n) {
    int b = n / NPOINTS;
    int p = n - b * NPOINTS;
    return b * (TT * NPOINTS) + 11 * NPOINTS + p;
}

// ---------------------------------------------------------------------------
// K1: agg1[dst] += x[t=11][src] (reads x directly; also warms L2 with LSTM
// weights). g_agg1 is zeroed: initially by module load, thereafter by
// node_kernel's read-then-zero.
// ---------------------------------------------------------------------------
__global__ void scatter1_kernel(const int* __restrict__ ei,
                                const float* __restrict__ x,
                                const float* __restrict__ Wih,
                                const float* __restrict__ Whh) {
    gdc_launch();
    int i = blockIdx.x * blockDim.x + threadIdx.x;
    // warm L2 with LSTM weights (Whh 64KB, Wih 8KB)
    if (i < 512) prefetch_l2((const char*)Whh + i * 128);
    else if (i < 576) prefetch_l2((const char*)Wih + (i - 512) * 128);
    if (i * 4 >= E_EDGES) return;
    int4 s4 = ((const int4*)ei)[i];
    int4 d4 = ((const int4*)(ei + E_EDGES))[i];
    atomicAdd(&g_agg1[d4.x], __ldg(&x[x11_index(s4.x)]));
    atomicAdd(&g_agg1[d4.y], __ldg(&x[x11_index(s4.y)]));
    atomicAdd(&g_agg1[d4.z], __ldg(&x[x11_index(s4.z)]));
    atomicAdd(&g_agg1[d4.w], __ldg(&x[x11_index(s4.w)]));
}

// ---------------------------------------------------------------------------
// K2: node MLP; writes y (edge payload), acc (root part), out init (= wt).
// Computes the 32 weather/time scalars in its prologue (pre-gdc_wait) and
// re-zeroes g_agg1 after reading (so the next graph replay sees zeros).
// ---------------------------------------------------------------------------
__global__ void node_kernel(const float* __restrict__ x,
                            const float* __restrict__ weather,
                            const float* __restrict__ timeenc,
                            const float* __restrict__ W1rel,
                            const float* __restrict__ b1,
                            const float* __restrict__ W1root,
                            const float* __restrict__ W2rel,
                            const float* __restrict__ b2,
                            const float* __restrict__ W2root,
                            const float* __restrict__ Wlin,
                            const float* __restrict__ blin,
                            float* __restrict__ out) {
    gdc_launch();
    __shared__ float sW1rel[GH], sb1[GH], sW1root[GH];
    __shared__ float sW2rel[GH * NO], sW2root[GH * NO], sb2[NO];
    __shared__ float swt[NB];
    int tid = threadIdx.x;
    if (tid < GH) {
        sW1rel[tid] = W1rel[tid];
        sb1[tid] = b1[tid];
        sW1root[tid] = W1root[tid];
    }
    if (tid < GH * NO) {
        sW2rel[tid] = W2rel[tid];
        sW2root[tid] = W2root[tid];
    }
    if (tid < NO) sb2[tid] = b2[tid];
    if (tid >= 64 && tid < 64 + NB) {   // separate warp pair computes wt
        int b = tid - 64;
        float s = __ldg(&blin[0]);
        #pragma unroll
        for (int jj = 0; jj < 4; jj++)
            s += __ldg(&weather[b * TT * 4 + 11 * 4 + jj]) * __ldg(&Wlin[64 + jj]);
        #pragma unroll
        for (int jj = 0; jj < 8; jj++)
            s += __ldg(&timeenc[b * TT * 8 + 11 * 8 + jj]) * __ldg(&Wlin[68 + jj]);
        swt[b] = s;
    }
    int n = blockIdx.x * blockDim.x + tid;
    float xv = (n < N_NODES) ? __ldg(&x[x11_index(n)]) : 0.f;
    __syncthreads();
    gdc_wait();

    if (n >= N_NODES) return;
    float a = g_agg1[n];
    g_agg1[n] = 0.f;   // reset for next replay (module-load zero on first run)
    float y[NO], p[NO];
    #pragma unroll
    for (int j = 0; j < NO; j++) { y[j] = 0.f; p[j] = sb2[j]; }
    #pragma unroll
    for (int k = 0; k < GH; k++) {
        float h1 = fmaf(a, sW1rel[k], fmaf(xv, sW1root[k], sb1[k]));
        h1 = fmaxf(h1, 0.f);
        #pragma unroll
        for (int j = 0; j < NO; j++) {
            y[j] = fmaf(h1, sW2rel[k * NO + j], y[j]);
            p[j] = fmaf(h1, sW2root[k * NO + j], p[j]);
        }
    }
    float4* yp = (float4*)&g_y[n * NO];
    yp[0] = make_float4(y[0], y[1], y[2], y[3]);
    yp[1] = make_float4(y[4], y[5], y[6], y[7]);
    float4* ap = (float4*)&g_acc[n * NO];
    ap[0] = make_float4(p[0], p[1], p[2], p[3]);
    ap[1] = make_float4(p[4], p[5], p[6], p[7]);
    out[n] = swt[n & (NB - 1)];
}

// ---------------------------------------------------------------------------
// K3: acc[dst] += y[src]   (8 floats/edge, vector reductions)
// ---------------------------------------------------------------------------
__device__ __forceinline__ void red_add_v4(float* addr, float4 v) {
    asm volatile("red.global.add.v4.f32 [%0], {%1,%2,%3,%4};"
                 :: "l"(addr), "f"(v.x), "f"(v.y), "f"(v.z), "f"(v.w)
                 : "memory");
}

__global__ void scatter2_kernel(const int* __restrict__ ei) {
    gdc_launch();
    int e = blockIdx.x * blockDim.x + threadIdx.x;
    if (e >= E_EDGES) { gdc_wait(); return; }
    int s = __ldg(&ei[e]);
    int d = __ldg(&ei[E_EDGES + e]);
    gdc_wait();
    const float4* yp = (const float4*)&g_y[s * NO];
    float4 va = __ldg(yp);
    float4 vb = __ldg(yp + 1);
    red_add_v4(&g_acc[d * NO], va);
    red_add_v4(&g_acc[d * NO + 4], vb);
}

// ---------------------------------------------------------------------------
// K4: LSTM scan. 3 independent chains per block (named-barrier groups of
// 4 warps / 128 threads). Weight register preload + ring zero + swlin fill
// run BEFORE gdc_wait (overlapped with scatter2 via PDL).
// ---------------------------------------------------------------------------
#define GBAR(gid) asm volatile("bar.sync %0, 128;" :: "r"((gid) + 1) : "memory")

__global__ void __launch_bounds__(384, 1) lstm_kernel(
    const float* __restrict__ Wih, const float* __restrict__ Whh,
    const float* __restrict__ bih, const float* __restrict__ bhh,
    const float* __restrict__ Wlin, float* __restrict__ out) {
    __shared__ __align__(16) float hring[NGROUPS][RING][68];
    __shared__ __align__(16) float xtile[NGROUPS][2][RING * NO];
    __shared__ float swlin[HH];

    int tid = threadIdx.x;
    int g = tid >> 7;            // group 0..2
    int lt = tid & 127;          // thread within group
    int l = tid & 31;
    int wl = (tid >> 5) & 3;     // warp within group
    int j = wl * 16 + (l >> 1);  // hidden unit
    int p = l & 1;               // gate-pair selector
    int gidxA = (2 * p) * 64 + j;        // p=0: i ; p=1: g
    int gidxB = gidxA + 64;              // p=0: f ; p=1: o

    // packed weights over the reduction dim (64 ull = 128 regs, L2-hot;
    // overlapped with scatter2 execution via PDL)
    unsigned long long whhA[HH / 2], whhB[HH / 2];
    #pragma unroll
    for (int k = 0; k < HH / 2; k++) {
        whhA[k] = pack2(__ldg(&Whh[(2 * k) * 256 + gidxA]),
                        __ldg(&Whh[(2 * k + 1) * 256 + gidxA]));
        whhB[k] = pack2(__ldg(&Whh[(2 * k) * 256 + gidxB]),
                        __ldg(&Whh[(2 * k + 1) * 256 + gidxB]));
    }
    unsigned long long wihA[NO / 2], wihB[NO / 2];
    #pragma unroll
    for (int k = 0; k < NO / 2; k++) {
        wihA[k] = pack2(__ldg(&Wih[(2 * k) * 256 + gidxA]),
                        __ldg(&Wih[(2 * k + 1) * 256 + gidxA]));
        wihB[k] = pack2(__ldg(&Wih[(2 * k) * 256 + gidxB]),
                        __ldg(&Wih[(2 * k + 1) * 256 + gidxB]));
    }
    // hoisted packed biases
    unsigned long long bA2 = pack2(__ldg(&bih[gidxA]) + __ldg(&bhh[gidxA]), 0.f);
    unsigned long long bB2 = pack2(__ldg(&bih[gidxB]) + __ldg(&bhh[gidxB]), 0.f);
    // activation constants: actA = fma(mA, tanh(sA*mA), kA)
    float mA = p ? 1.f : 0.5f;   // p=0: sigmoid(i)/(f) ; p=1: tanh(g), sigmoid(o)
    float kA = p ? 0.f : 0.5f;

    for (int k = lt; k < RING * 68; k += 128)
        ((float*)hring[g])[k] = 0.f;
    if (tid < HH) swlin[tid] = __ldg(&Wlin[tid]);
    __syncthreads();   // whole block once; groups independent afterwards

    int chunk = blockIdx.x * NGROUPS + g;
    int start = chunk * CHUNK;
    int end = start + CHUNK;
    if (end > N_NODES) end = N_NODES;
    int s0 = start - LOOKBACK;
    if (s0 < 0) s0 = 0;
    int wfirst = s0 & ~(RING - 1);

    gdc_wait();   // g_acc / out ready (scatter2 + node complete)
    if (start >= N_NODES) return;   // whole group exits uniformly

    // prime double-buffered x staging: windows wfirst and wfirst+RING
    {
        int b0 = (wfirst >> 5) & 1;
        if (lt < 64) {
            uint32_t dst0 = (uint32_t)__cvta_generic_to_shared(&xtile[g][b0][lt * 4]);
            cp_async16(dst0, &g_acc[wfirst * NO + lt * 4]);
            cp_commit();
            uint32_t dst1 = (uint32_t)__cvta_generic_to_shared(&xtile[g][b0 ^ 1][lt * 4]);
            cp_async16(dst1, &g_acc[(wfirst + RING) * NO + lt * 4]);
            cp_commit();
        }
        cp_wait0();
        GBAR(g);
    }

    float c = 0.f;

    for (int w = wfirst; w < end; w += RING) {
        int buf = (w >> 5) & 1;
        if (w != wfirst) {
            // prefetched buffer ready (issued a window ago); make visible,
            // kick prefetch for the window after next (pad covers overrun)
            cp_wait0();
            GBAR(g);
            if (lt < 64) {
                uint32_t dst = (uint32_t)__cvta_generic_to_shared(&xtile[g][buf ^ 1][lt * 4]);
                cp_async16(dst, &g_acc[(w + RING) * NO + lt * 4]);
                cp_commit();
            }
        }
        int nlo = (w < s0) ? s0 : w;
        int nhi = (w + RING < end) ? (w + RING) : end;
        const float* xbase = &xtile[g][buf][0];

        for (int n = nlo; n < nhi; n++) {
            int r = n & (RING - 1);
            const ulonglong2* xp = (const ulonglong2*)(xbase + r * NO);
            ulonglong2 xv0 = xp[0];
            ulonglong2 xv1 = xp[1];
            unsigned long long aA = bA2;
            unsigned long long aB = bB2;
            aA = fma2(xv0.x, wihA[0], aA); aB = fma2(xv0.x, wihB[0], aB);
            aA = fma2(xv0.y, wihA[1], aA); aB = fma2(xv0.y, wihB[1], aB);
            aA = fma2(xv1.x, wihA[2], aA); aB = fma2(xv1.x, wihB[2], aB);
            aA = fma2(xv1.y, wihA[3], aA); aB = fma2(xv1.y, wihB[3], aB);
            const ulonglong2* hp = (const ulonglong2*)hring[g][(n - 1) & (RING - 1)];
            #pragma unroll
            for (int k = 0; k < 16; k++) {
                ulonglong2 hv = hp[k];   // dual-broadcast LDS.128
                aA = fma2(hv.x, whhA[2 * k + 0], aA);
                aA = fma2(hv.y, whhA[2 * k + 1], aA);
                aB = fma2(hv.x, whhB[2 * k + 0], aB);
                aB = fma2(hv.y, whhB[2 * k + 1], aB);
            }
            float sA = unpack_sum(aA);
            float sB = unpack_sum(aB);
            // p=0: actA=sigmoid(i), actB=sigmoid(f) ; p=1: actA=tanh(g), actB=sigmoid(o)
            float actA = fmaf(mA, tanh_a(sA * mA), kA);
            float actB = fmaf(0.5f, tanh_a(0.5f * sB), 0.5f);
            float rAv = __shfl_xor_sync(0xffffffffu, actA, 1);   // p=0 gets tanh(g)
            float rBv = __shfl_xor_sync(0xffffffffu, actB, 1);   // p=0 gets sigmoid(o)
            // valid on p=0 lanes only: c = f*c + i*g ; hn = o*tanh(c)
            c = fmaf(actB, c, actA * rAv);
            float hn = rBv * tanh_a(c);
            if (p == 0) hring[g][r][j] = hn;
            GBAR(g);
        }

        if (nhi > start) {
            // bulk output flush for [w, nhi) ∩ [start, end)
            int nn = w + (lt >> 2);
            int q = lt & 3;
            const float* hrow = hring[g][lt >> 2];
            float acc = 0.f;
            #pragma unroll
            for (int k = 0; k < 16; k++)
                acc = fmaf(hrow[q * 16 + k], swlin[q * 16 + k], acc);
            acc += __shfl_xor_sync(0xffffffffu, acc, 1);
            acc += __shfl_xor_sync(0xffffffffu, acc, 2);
            if (q == 0 && nn >= start && nn < nhi)
                out[nn] += acc;            // exclusive writer; out pre-set to wt
        }
    }
}

// ---------------------------------------------------------------------------
template <typename... Args>
static inline void launch_pdl(void (*kern)(Args...), dim3 grid, dim3 block,
                              Args... args) {
    cudaLaunchConfig_t cfg = {};
    cfg.gridDim = grid;
    cfg.blockDim = block;
    cfg.dynamicSmemBytes = 0;
    cfg.stream = 0;
    cudaLaunchAttribute attr[1];
    attr[0].id = cudaLaunchAttributeProgrammaticStreamSerialization;
    attr[0].val.programmaticStreamSerializationAllowed = 1;
    cfg.attrs = attr;
    cfg.numAttrs = 1;
    cudaLaunchKernelEx(&cfg, kern, args...);
}

extern "C" void kernel_launch(void* const* d_in, const int* in_sizes, int n_in,
                              void* d_out, int out_size) {
    const float* x        = (const float*)d_in[0];
    const int*   ei       = (const int*)  d_in[1];
    const float* weather  = (const float*)d_in[2];
    const float* timeenc  = (const float*)d_in[3];
    const float* W1rel    = (const float*)d_in[4];
    const float* b1       = (const float*)d_in[5];
    const float* W1root   = (const float*)d_in[6];
    const float* W2rel    = (const float*)d_in[7];
    const float* b2       = (const float*)d_in[8];
    const float* W2root   = (const float*)d_in[9];
    const float* Wih      = (const float*)d_in[10];
    const float* Whh      = (const float*)d_in[11];
    const float* bih      = (const float*)d_in[12];
    const float* bhh      = (const float*)d_in[13];
    const float* Wlin     = (const float*)d_in[14];
    const float* blin     = (const float*)d_in[15];
    float* out = (float*)d_out;

    scatter1_kernel<<<(E_EDGES / 4 + 255) / 256, 256>>>(ei, x, Wih, Whh);
    launch_pdl(node_kernel, dim3((N_NODES + 255) / 256), dim3(256),
               x, weather, timeenc, W1rel, b1, W1root, W2rel, b2, W2root,
               Wlin, blin, out);
    launch_pdl(scatter2_kernel, dim3((E_EDGES + 255) / 256), dim3(256), ei);
    launch_pdl(lstm_kernel, dim3(NBLK), dim3(384), Wih, Whh, bih, bhh, Wlin, out);
}